// round 7
// baseline (speedup 1.0000x reference)
#include <cuda_runtime.h>
#include <cuda_bf16.h>

// GraphAggregation: out[b, :] = mean over 196 nodes of in[b].reshape(196, 4)
// Input : (B, 784) fp32. Row = 3136 B = 98 x 32B float8 chunks.
// Output: (B, 4) fp32.
//
// R3 structure (best measured: DRAM 86%): one warp per row, lane l loads
// float8 chunks l, l+32, l+64 (LDG.E.256, 1KB/warp per instruction),
// lanes 0-1 take the tail. This round: .L2::256B prefetch-size hint on the
// streaming loads (amortize DRAM command overhead) + 512-thread blocks
// (halve block churn, raise achieved occupancy / in-flight loads).

#define N_NODES 196
#define ROW_FLOATS (N_NODES * 4)   // 784
#define DINV (1.0f / 196.0f)

// 256-bit streaming load of 8 floats with 256B L2 fetch-granularity hint.
#define LDG256(r, ptr)                                                        \
    asm volatile("ld.global.nc.L2::256B.v8.f32 {%0,%1,%2,%3,%4,%5,%6,%7}, [%8];" \
                 : "=f"((r)[0]), "=f"((r)[1]), "=f"((r)[2]), "=f"((r)[3]),    \
                   "=f"((r)[4]), "=f"((r)[5]), "=f"((r)[6]), "=f"((r)[7])     \
                 : "l"(ptr))

__global__ __launch_bounds__(512)
void graph_agg_kernel(const float* __restrict__ in, float4* __restrict__ out, int B)
{
    const int warp_in_block = threadIdx.x >> 5;
    const int lane = threadIdx.x & 31;
    const int row = blockIdx.x * (blockDim.x >> 5) + warp_in_block;
    if (row >= B) return;

    // Lane's first chunk: 8 floats at chunk index `lane`.
    const float* __restrict__ p = in + (size_t)row * ROW_FLOATS + lane * 8;

    float a[8], b[8], c[8];
    float d[8] = {0.f, 0.f, 0.f, 0.f, 0.f, 0.f, 0.f, 0.f};

    LDG256(a, p);            // chunks   0..31
    LDG256(b, p + 256);      // chunks  32..63
    LDG256(c, p + 512);      // chunks  64..95
    if (lane < 2) {
        LDG256(d, p + 768);  // chunks  96..97 (lanes 0,1)
    }

    // Each float8 chunk = two node float4s: component t at indices {t, t+4}.
    float sx = ((a[0] + a[4]) + (b[0] + b[4])) + ((c[0] + c[4]) + (d[0] + d[4]));
    float sy = ((a[1] + a[5]) + (b[1] + b[5])) + ((c[1] + c[5]) + (d[1] + d[5]));
    float sz = ((a[2] + a[6]) + (b[2] + b[6])) + ((c[2] + c[6]) + (d[2] + d[6]));
    float sw = ((a[3] + a[7]) + (b[3] + b[7])) + ((c[3] + c[7]) + (d[3] + d[7]));

    // Warp tree reduction of the 4-vector.
    #pragma unroll
    for (int off = 16; off > 0; off >>= 1) {
        sx += __shfl_xor_sync(0xFFFFFFFFu, sx, off);
        sy += __shfl_xor_sync(0xFFFFFFFFu, sy, off);
        sz += __shfl_xor_sync(0xFFFFFFFFu, sz, off);
        sw += __shfl_xor_sync(0xFFFFFFFFu, sw, off);
    }

    if (lane == 0) {
        float4 r;
        r.x = sx * DINV;
        r.y = sy * DINV;
        r.z = sz * DINV;
        r.w = sw * DINV;
        out[row] = r;
    }
}

extern "C" void kernel_launch(void* const* d_in, const int* in_sizes, int n_in,
                              void* d_out, int out_size)
{
    const float* in = (const float*)d_in[0];
    float4* out = (float4*)d_out;
    const int B = in_sizes[0] / ROW_FLOATS;      // 131072

    const int warps_per_block = 16;              // 512 threads
    const int blocks = (B + warps_per_block - 1) / warps_per_block;  // 8192
    graph_agg_kernel<<<blocks, warps_per_block * 32>>>(in, out, B);
}

// round 8
// speedup vs baseline: 1.0354x; 1.0354x over previous
#include <cuda_runtime.h>
#include <cuda_bf16.h>

// GraphAggregation: out[b, :] = mean over 196 nodes of in[b].reshape(196, 4)
// Input : (B, 784) fp32. Row = 3136 B = 98 x 32B float8 chunks.
// Output: (B, 4) fp32.
//
// Best-measured body (R3): one warp per row, lane l loads float8 chunks
// l, l+32, l+64 via 256-bit LDG (1 KB per warp-instruction, fully
// coalesced), lanes 0-1 take the 2-chunk tail. Warp shfl reduction,
// lane 0 writes the mean with a streaming (evict-first) store so the
// output never displaces L2 lines from the 411 MB read stream.
// Kernel is at the sustained HBM read bound (~6.5-6.8 TB/s).

#define N_NODES 196
#define ROW_FLOATS (N_NODES * 4)   // 784
#define DINV (1.0f / 196.0f)

// 256-bit load of 8 floats (sm_100+ LDG.E.256), non-coherent path.
#define LDG256(r, ptr)                                                        \
    asm volatile("ld.global.nc.v8.f32 {%0,%1,%2,%3,%4,%5,%6,%7}, [%8];"       \
                 : "=f"((r)[0]), "=f"((r)[1]), "=f"((r)[2]), "=f"((r)[3]),    \
                   "=f"((r)[4]), "=f"((r)[5]), "=f"((r)[6]), "=f"((r)[7])     \
                 : "l"(ptr))

__global__ __launch_bounds__(256)
void graph_agg_kernel(const float* __restrict__ in, float4* __restrict__ out, int B)
{
    const int warp_in_block = threadIdx.x >> 5;
    const int lane = threadIdx.x & 31;
    const int row = blockIdx.x * (blockDim.x >> 5) + warp_in_block;
    if (row >= B) return;

    // Lane's first chunk: 8 floats at chunk index `lane`.
    const float* __restrict__ p = in + (size_t)row * ROW_FLOATS + lane * 8;

    float a[8], b[8], c[8];
    float d[8] = {0.f, 0.f, 0.f, 0.f, 0.f, 0.f, 0.f, 0.f};

    LDG256(a, p);            // chunks   0..31
    LDG256(b, p + 256);      // chunks  32..63
    LDG256(c, p + 512);      // chunks  64..95
    if (lane < 2) {
        LDG256(d, p + 768);  // chunks  96..97 (lanes 0,1)
    }

    // Each float8 chunk = two node float4s: component t at indices {t, t+4}.
    float sx = ((a[0] + a[4]) + (b[0] + b[4])) + ((c[0] + c[4]) + (d[0] + d[4]));
    float sy = ((a[1] + a[5]) + (b[1] + b[5])) + ((c[1] + c[5]) + (d[1] + d[5]));
    float sz = ((a[2] + a[6]) + (b[2] + b[6])) + ((c[2] + c[6]) + (d[2] + d[6]));
    float sw = ((a[3] + a[7]) + (b[3] + b[7])) + ((c[3] + c[7]) + (d[3] + d[7]));

    // Warp tree reduction of the 4-vector.
    #pragma unroll
    for (int off = 16; off > 0; off >>= 1) {
        sx += __shfl_xor_sync(0xFFFFFFFFu, sx, off);
        sy += __shfl_xor_sync(0xFFFFFFFFu, sy, off);
        sz += __shfl_xor_sync(0xFFFFFFFFu, sz, off);
        sw += __shfl_xor_sync(0xFFFFFFFFu, sw, off);
    }

    if (lane == 0) {
        // Streaming store (evict-first): don't pollute L2 with output lines.
        asm volatile("st.global.cs.v4.f32 [%0], {%1,%2,%3,%4};"
                     :: "l"(out + row),
                        "f"(sx * DINV), "f"(sy * DINV),
                        "f"(sz * DINV), "f"(sw * DINV)
                     : "memory");
    }
}

extern "C" void kernel_launch(void* const* d_in, const int* in_sizes, int n_in,
                              void* d_out, int out_size)
{
    const float* in = (const float*)d_in[0];
    float4* out = (float4*)d_out;
    const int B = in_sizes[0] / ROW_FLOATS;      // 131072

    const int warps_per_block = 8;               // 256 threads
    const int blocks = (B + warps_per_block - 1) / warps_per_block;  // 16384
    graph_agg_kernel<<<blocks, warps_per_block * 32>>>(in, out, B);
}

// round 9
// speedup vs baseline: 1.1033x; 1.0656x over previous
#include <cuda_runtime.h>
#include <cuda_bf16.h>

// GraphAggregation: out[b, :] = mean over 196 nodes of in[b].reshape(196, 4)
// Input : (B, 784) fp32. Row = 3136 B = 98 x 32B chunks (float8), 32B-aligned.
// Output: (B, 4) fp32.
//
// Converged configuration (best of 8 rounds: 63.49us wall, DRAM 86%,
// HBM 6.8 TB/s): one warp per row, 256-bit LDG (sm_100+ LDG.E.256):
// lane l loads float8 chunks l, l+32, l+64 unconditionally (1KB/warp per
// instruction, fully coalesced), lanes 0-1 take the tail chunks 96,97.
// Warp shfl reduction, lane 0 writes the float4 mean via a plain store.
// Pure HBM-bound stream of 411 MB; all structural alternatives tested
// (persistent+pipelined, 2 rows/warp, 512-thr blocks, L2 hints, .cs
// stores) measured slower.

#define N_NODES 196
#define ROW_FLOATS (N_NODES * 4)   // 784
#define DINV (1.0f / 196.0f)

// 256-bit load of 8 floats.
#define LDG256(r, ptr)                                                        \
    asm volatile("ld.global.nc.v8.f32 {%0,%1,%2,%3,%4,%5,%6,%7}, [%8];"       \
                 : "=f"((r)[0]), "=f"((r)[1]), "=f"((r)[2]), "=f"((r)[3]),    \
                   "=f"((r)[4]), "=f"((r)[5]), "=f"((r)[6]), "=f"((r)[7])     \
                 : "l"(ptr))

__global__ __launch_bounds__(256)
void graph_agg_kernel(const float* __restrict__ in, float4* __restrict__ out, int B)
{
    const int warp_in_block = threadIdx.x >> 5;
    const int lane = threadIdx.x & 31;
    const int row = blockIdx.x * (blockDim.x >> 5) + warp_in_block;
    if (row >= B) return;

    // Lane's first chunk: 8 floats at chunk index `lane`.
    const float* __restrict__ p = in + (size_t)row * ROW_FLOATS + lane * 8;

    float a[8], b[8], c[8];
    float d[8] = {0.f, 0.f, 0.f, 0.f, 0.f, 0.f, 0.f, 0.f};

    LDG256(a, p);            // chunks   0..31
    LDG256(b, p + 256);      // chunks  32..63
    LDG256(c, p + 512);      // chunks  64..95
    if (lane < 2) {
        LDG256(d, p + 768);  // chunks  96..97 (lanes 0,1)
    }

    // Each float8 chunk = two node float4s: component t at indices {t, t+4}.
    float sx = ((a[0] + a[4]) + (b[0] + b[4])) + ((c[0] + c[4]) + (d[0] + d[4]));
    float sy = ((a[1] + a[5]) + (b[1] + b[5])) + ((c[1] + c[5]) + (d[1] + d[5]));
    float sz = ((a[2] + a[6]) + (b[2] + b[6])) + ((c[2] + c[6]) + (d[2] + d[6]));
    float sw = ((a[3] + a[7]) + (b[3] + b[7])) + ((c[3] + c[7]) + (d[3] + d[7]));

    // Warp tree reduction of the 4-vector.
    #pragma unroll
    for (int off = 16; off > 0; off >>= 1) {
        sx += __shfl_xor_sync(0xFFFFFFFFu, sx, off);
        sy += __shfl_xor_sync(0xFFFFFFFFu, sy, off);
        sz += __shfl_xor_sync(0xFFFFFFFFu, sz, off);
        sw += __shfl_xor_sync(0xFFFFFFFFu, sw, off);
    }

    if (lane == 0) {
        float4 r;
        r.x = sx * DINV;
        r.y = sy * DINV;
        r.z = sz * DINV;
        r.w = sw * DINV;
        out[row] = r;
    }
}

extern "C" void kernel_launch(void* const* d_in, const int* in_sizes, int n_in,
                              void* d_out, int out_size)
{
    const float* in = (const float*)d_in[0];
    float4* out = (float4*)d_out;
    const int B = in_sizes[0] / ROW_FLOATS;      // 131072

    const int warps_per_block = 8;               // 256 threads
    const int blocks = (B + warps_per_block - 1) / warps_per_block;  // 16384
    graph_agg_kernel<<<blocks, warps_per_block * 32>>>(in, out, B);
}